// round 16
// baseline (speedup 1.0000x reference)
#include <cuda_runtime.h>
#include <cuda_fp16.h>
#include <math.h>
#include <stdint.h>

#define NN 50000
#define EE 800000
#define INF 128
#define HID 256
#define OUTD 40

// ---------------- scratch (static device globals; no allocation) -------------
__device__ int    g_deg[NN];        // indeg (self-loop added analytically)
__device__ float  g_dinv[NN];
__device__ int    g_rowptr[NN + 1];
__device__ int    g_cursor[NN];
__device__ int    g_col[EE];
__device__ int    g_bsum[64];
__device__ int    g_ctr[2];         // gemm completion counters (loader zero-init)
__device__ __align__(16) __half g_xh[(size_t)NN * INF];    // x in fp16
__device__ __align__(16) __half g_aggxh[(size_t)NN * INF]; // Â x (fp16)
__device__ __align__(16) __half g_mh[(size_t)NN * HID];    // conv outputs m1/m2 (fp16)
__device__ __align__(16) __half g_aggh[(size_t)NN * HID];  // Â f1(m1) (fp16)
__device__ __align__(16) __half g_p3h[(size_t)NN * OUTD];  // dinv*(f2(m2)@W3) fp16
__device__ __align__(16) uint32_t g_w1h[64 * 256];         // W1 k-pair fp16
__device__ __align__(16) uint32_t g_w2h[128 * 256];        // W2 k-pair fp16
__device__ __align__(16) uint32_t g_w3h[128 * OUTD];       // W3 k-pair fp16
__device__ float  g_sumf[HID];     // fused BN stats (fp32, atomic)
__device__ float  g_sum2f[HID];
__device__ float  g_scale[HID];
__device__ float  g_shift[HID];

// ---------------- half pack/unpack helpers -------------------------------------
__device__ __forceinline__ void h4f(uint2 u, float f[4]) {
    float2 p0 = __half22float2(*(__half2*)&u.x);
    float2 p1 = __half22float2(*(__half2*)&u.y);
    f[0] = p0.x; f[1] = p0.y; f[2] = p1.x; f[3] = p1.y;
}
__device__ __forceinline__ uint2 f4h(const float f[4]) {
    __half2 h0 = __floats2half2_rn(f[0], f[1]);
    __half2 h1 = __floats2half2_rn(f[2], f[3]);
    uint2 u;
    u.x = *(uint32_t*)&h0;
    u.y = *(uint32_t*)&h1;
    return u;
}
__device__ __forceinline__ void h8f(uint4 u, float f[8]) {
    h4f(make_uint2(u.x, u.y), f);
    h4f(make_uint2(u.z, u.w), f + 4);
}
__device__ __forceinline__ uint4 f8h(const float f[8]) {
    uint2 a = f4h(f), b = f4h(f + 4);
    return make_uint4(a.x, a.y, b.x, b.y);
}
__device__ __forceinline__ uint32_t pack2h(float a, float b) {
    __half2 h = __floats2half2_rn(a, b);
    return *(uint32_t*)&h;
}
__device__ __forceinline__ void cp16(void* smem, const void* g) {
    uint32_t sa = (uint32_t)__cvta_generic_to_shared(smem);
    asm volatile("cp.async.cg.shared.global [%0], [%1], 16;" :: "r"(sa), "l"(g));
}

// ---------------- merged preprocessing: wconv + xtoh + deg ----------------------
__global__ void k_prep(const int* __restrict__ ei,
                       const float* __restrict__ x,
                       const float* __restrict__ W1,
                       const float* __restrict__ W2,
                       const float* __restrict__ W3,
                       int e, int n, int total8) {
    int i = blockIdx.x * blockDim.x + threadIdx.x;
    if (i < total8) {
        float4 a = ((const float4*)x)[i * 2];
        float4 b = ((const float4*)x)[i * 2 + 1];
        float f[8] = {a.x, a.y, a.z, a.w, b.x, b.y, b.z, b.w};
        ((uint4*)g_xh)[i] = f8h(f);
    }
    if (i < e) {
        int d = ei[e + i];
        if ((unsigned)d < (unsigned)n) atomicAdd(&g_deg[d], 1);
    }
    if (i < 64 * 256) {
        int k2 = i >> 8, nc = i & 255;
        g_w1h[i] = pack2h(W1[(size_t)(2 * k2) * 256 + nc], W1[(size_t)(2 * k2 + 1) * 256 + nc]);
    }
    if (i < 128 * 256) {
        int k2 = i >> 8, nc = i & 255;
        g_w2h[i] = pack2h(W2[(size_t)(2 * k2) * 256 + nc], W2[(size_t)(2 * k2 + 1) * 256 + nc]);
    }
    if (i < 128 * OUTD) {
        int k2 = i / OUTD, nc = i % OUTD;
        g_w3h[i] = pack2h(W3[(size_t)(2 * k2) * OUTD + nc], W3[(size_t)(2 * k2 + 1) * OUTD + nc]);
    }
}

// ---------------- CSR build -----------------------------------------------------
__global__ __launch_bounds__(1024) void k_scan1(int n) {
    __shared__ int warpsums[32];
    int b = blockIdx.x, tid = threadIdx.x;
    int i = b * 1024 + tid;
    int v = 0;
    if (i < n) {
        int d = g_deg[i];
        v = d;
        g_dinv[i] = rsqrtf((float)(d + 1));
    }
    int x = v;
    #pragma unroll
    for (int o = 1; o < 32; o <<= 1) {
        int y = __shfl_up_sync(0xFFFFFFFFu, x, o);
        if ((tid & 31) >= o) x += y;
    }
    if ((tid & 31) == 31) warpsums[tid >> 5] = x;
    __syncthreads();
    if (tid < 32) {
        int w = warpsums[tid];
        #pragma unroll
        for (int o = 1; o < 32; o <<= 1) {
            int y = __shfl_up_sync(0xFFFFFFFFu, w, o);
            if (tid >= o) w += y;
        }
        warpsums[tid] = w;
    }
    __syncthreads();
    int incl = x + ((tid >= 32) ? warpsums[(tid >> 5) - 1] : 0);
    if (i < n) g_rowptr[i + 1] = incl;
    if (tid == 1023) g_bsum[b] = incl;
}

__global__ __launch_bounds__(1024) void k_scan23(int n, int nb) {
    __shared__ int w0s;
    __shared__ int s_off;
    int tid = threadIdx.x;
    int v = 0, x = 0;
    if (tid < 64) {
        v = (tid < nb) ? g_bsum[tid] : 0;
        x = v;
        #pragma unroll
        for (int o = 1; o < 32; o <<= 1) {
            int y = __shfl_up_sync(0xFFFFFFFFu, x, o);
            if ((tid & 31) >= o) x += y;
        }
        if (tid == 31) w0s = x;
    }
    __syncthreads();
    if (tid < 64) {
        int incl = x + ((tid >= 32) ? w0s : 0);
        if (tid == blockIdx.x) s_off = incl - v;
    }
    __syncthreads();
    int i = blockIdx.x * 1024 + tid;
    if (i < n) {
        int indeg = g_deg[i];
        int val = g_rowptr[i + 1] + s_off;
        g_rowptr[i + 1] = val;
        g_cursor[i] = val - indeg;
        g_deg[i] = 0;                               // reset for next replay
    }
    if (i == 0) g_rowptr[0] = 0;
}

__global__ void k_scatter(const int* __restrict__ ei, int e, int n) {
    int i = blockIdx.x * blockDim.x + threadIdx.x;
    if (i < e) {
        int s = ei[i], d = ei[e + i];
        if ((unsigned)d < (unsigned)n) {
            s = min(max(s, 0), n - 1);
            int pos = atomicAdd(&g_cursor[d], 1);
            g_col[pos] = s;
        }
    }
}

// ---------------- aggregation kernels (warp-per-node, 8 warps/block) ------------
__global__ __launch_bounds__(256) void k_aggX(int n) {
    int node = blockIdx.x * 8 + (threadIdx.x >> 5);
    int lane = threadIdx.x & 31;
    if (node >= n) return;
    const uint2* __restrict__ x2 = (const uint2*)g_xh;   // 32 uint2 per row
    float di = g_dinv[node];
    float acc[4], f[4];
    h4f(x2[(size_t)node * 32 + lane], f);
    #pragma unroll
    for (int j = 0; j < 4; j++) acc[j] = di * f[j];
    int e0 = g_rowptr[node], e1 = g_rowptr[node + 1];
    int e = e0;
    for (; e + 1 < e1; e += 2) {
        int s0 = g_col[e], s1 = g_col[e + 1];
        float d0 = g_dinv[s0], d1 = g_dinv[s1];
        float f0[4], f1[4];
        h4f(x2[(size_t)s0 * 32 + lane], f0);
        h4f(x2[(size_t)s1 * 32 + lane], f1);
        #pragma unroll
        for (int j = 0; j < 4; j++) acc[j] += d0 * f0[j] + d1 * f1[j];
    }
    if (e < e1) {
        int s = g_col[e];
        float d = g_dinv[s];
        h4f(x2[(size_t)s * 32 + lane], f);
        #pragma unroll
        for (int j = 0; j < 4; j++) acc[j] += d * f[j];
    }
    #pragma unroll
    for (int j = 0; j < 4; j++) acc[j] *= di;
    ((uint2*)g_aggxh)[(size_t)node * 32 + lane] = f4h(acc);
}

// agg with BN+ReLU applied in packed fp16 (half2), fp32 accumulation
__global__ __launch_bounds__(256) void k_agg256(int n) {
    int node = blockIdx.x * 8 + (threadIdx.x >> 5);
    int lane = threadIdx.x & 31;
    if (node >= n) return;
    const uint4* __restrict__ m4 = (const uint4*)g_mh;   // 32 uint4 per row
    __half2 sc2[4], sh2[4];
    {
        float4 s0 = ((const float4*)g_scale)[2 * lane];
        float4 s1 = ((const float4*)g_scale)[2 * lane + 1];
        float4 h0 = ((const float4*)g_shift)[2 * lane];
        float4 h1 = ((const float4*)g_shift)[2 * lane + 1];
        sc2[0] = __floats2half2_rn(s0.x, s0.y); sc2[1] = __floats2half2_rn(s0.z, s0.w);
        sc2[2] = __floats2half2_rn(s1.x, s1.y); sc2[3] = __floats2half2_rn(s1.z, s1.w);
        sh2[0] = __floats2half2_rn(h0.x, h0.y); sh2[1] = __floats2half2_rn(h0.z, h0.w);
        sh2[2] = __floats2half2_rn(h1.x, h1.y); sh2[3] = __floats2half2_rn(h1.z, h1.w);
    }
    const __half2 zero2 = __floats2half2_rn(0.f, 0.f);
    float di = g_dinv[node];
    float acc[8];
    #pragma unroll
    for (int j = 0; j < 8; j++) acc[j] = 0.f;

    auto accum = [&](uint4 u, float d) {
        uint32_t w[4] = {u.x, u.y, u.z, u.w};
        #pragma unroll
        for (int j = 0; j < 4; j++) {
            __half2 v = *(__half2*)&w[j];
            v = __hmax2(__hfma2(v, sc2[j], sh2[j]), zero2);
            float2 p = __half22float2(v);
            acc[2 * j]     = fmaf(d, p.x, acc[2 * j]);
            acc[2 * j + 1] = fmaf(d, p.y, acc[2 * j + 1]);
        }
    };

    accum(m4[(size_t)node * 32 + lane], di);   // self loop
    int e0 = g_rowptr[node], e1 = g_rowptr[node + 1];
    int e = e0;
    for (; e + 1 < e1; e += 2) {
        int s0 = g_col[e], s1 = g_col[e + 1];
        float d0 = g_dinv[s0], d1 = g_dinv[s1];
        uint4 u0 = m4[(size_t)s0 * 32 + lane];
        uint4 u1 = m4[(size_t)s1 * 32 + lane];
        accum(u0, d0);
        accum(u1, d1);
    }
    if (e < e1) {
        int s = g_col[e];
        accum(m4[(size_t)s * 32 + lane], g_dinv[s]);
    }
    #pragma unroll
    for (int j = 0; j < 8; j++) acc[j] *= di;
    ((uint4*)g_aggh)[(size_t)node * 32 + lane] = f8h(acc);
}

// ---------------- fp16 m16n8k16 MMA helper --------------------------------------
__device__ __forceinline__ void mma_f16(float c[4], const uint32_t a[4], const uint32_t b[2]) {
    asm volatile(
        "mma.sync.aligned.m16n8k16.row.col.f32.f16.f16.f32 "
        "{%0,%1,%2,%3}, {%4,%5,%6,%7}, {%8,%9}, {%0,%1,%2,%3};"
        : "+f"(c[0]), "+f"(c[1]), "+f"(c[2]), "+f"(c[3])
        : "r"(a[0]), "r"(a[1]), "r"(a[2]), "r"(a[3]), "r"(b[0]), "r"(b[1]));
}

#define TPAD 136    // B word stride: 136 % 32 == 8 -> conflict-free
#define ASTRIDE 20  // A word stride: {k*20 mod 32} covers all banks

// ---------------- fp16 TC GEMM (cp.async double-buffered, fused BN params) ------
// C_h[M,256] = A_h[M,K] @ Wh[K,256] + bias ; BN stats + params fused.
template <int LAYER>
__global__ __launch_bounds__(256) void k_gemm256_tc(
    const float* __restrict__ bias, const float* __restrict__ bn_g,
    const float* __restrict__ bn_be, int M) {
    constexpr int K = (LAYER == 1) ? INF : HID;
    constexpr int NSTEP = K / 32;
    const __half* __restrict__ A = (LAYER == 1) ? g_aggxh : g_aggh;
    const uint32_t* __restrict__ Bw = (LAYER == 1) ? g_w1h : g_w2h;  // [K/2][256]
    __half* __restrict__ C = g_mh;

    __shared__ uint32_t As[2][128][ASTRIDE];  // [stage][m][k2] (16 of 20 used)
    __shared__ uint32_t Bs[2][16][TPAD];      // [stage][k2][n]
    __shared__ float s_s[128], s_s2[128];
    __shared__ bool isLast;

    int t = threadIdx.x;
    int warp = t >> 5, lane = t & 31;
    int lr = lane >> 2, lc = lane & 3;
    int warpM = (warp >> 2) * 64;
    int warpN = (warp & 3) * 32;
    int rowBase = blockIdx.x * 128;
    int colBase = blockIdx.y * 128;

    if (t < 128) { s_s[t] = 0.f; s_s2[t] = 0.f; }

    float acc[4][4][4];
    #pragma unroll
    for (int mt = 0; mt < 4; mt++)
        #pragma unroll
        for (int nt = 0; nt < 4; nt++)
            #pragma unroll
            for (int j = 0; j < 4; j++) acc[mt][nt][j] = 0.f;

    auto load_stage = [&](int st, int kk) {
        #pragma unroll
        for (int h = 0; h < 2; h++) {
            int s = t + h * 256;
            int row = s >> 2;
            int c4 = (s & 3) << 2;                 // uint32 offset in row
            int r = min(rowBase + row, M - 1);     // clamp: dup rows, results unused
            cp16(&As[st][row][c4], A + (size_t)r * K + kk + (c4 << 1));
        }
        int kk2 = kk >> 1;
        #pragma unroll
        for (int h = 0; h < 2; h++) {
            int s = t + h * 256;
            int k2 = s >> 5;
            int n4 = (s & 31) << 2;
            cp16(&Bs[st][k2][n4], Bw + (size_t)(kk2 + k2) * 256 + colBase + n4);
        }
        asm volatile("cp.async.commit_group;");
    };

    load_stage(0, 0);
    #pragma unroll
    for (int i = 0; i < NSTEP; i++) {
        if (i + 1 < NSTEP) {
            load_stage((i + 1) & 1, (i + 1) * 32);
            asm volatile("cp.async.wait_group 1;");
        } else {
            asm volatile("cp.async.wait_group 0;");
        }
        __syncthreads();
        int st = i & 1;
        #pragma unroll
        for (int s = 0; s < 2; s++) {
            int kc2 = s * 8;
            uint32_t af[4][4], bf[4][2];
            #pragma unroll
            for (int nt = 0; nt < 4; nt++) {
                int nc = warpN + nt * 8 + lr;
                bf[nt][0] = Bs[st][kc2 + lc][nc];
                bf[nt][1] = Bs[st][kc2 + 4 + lc][nc];
            }
            #pragma unroll
            for (int mt = 0; mt < 4; mt++) {
                int m = warpM + mt * 16 + lr;
                af[mt][0] = As[st][m][kc2 + lc];
                af[mt][1] = As[st][m + 8][kc2 + lc];
                af[mt][2] = As[st][m][kc2 + 4 + lc];
                af[mt][3] = As[st][m + 8][kc2 + 4 + lc];
            }
            #pragma unroll
            for (int mt = 0; mt < 4; mt++)
                #pragma unroll
                for (int nt = 0; nt < 4; nt++)
                    mma_f16(acc[mt][nt], af[mt], bf[nt]);
        }
        __syncthreads();
    }

    // epilogue: bias add + half store + fused BN-stat accumulation (fp32)
    float ls[8], ls2[8];
    #pragma unroll
    for (int j = 0; j < 8; j++) { ls[j] = 0.f; ls2[j] = 0.f; }

    #pragma unroll
    for (int nt = 0; nt < 4; nt++) {
        int col = colBase + warpN + nt * 8 + 2 * lc;
        float b0 = bias[col], b1 = bias[col + 1];
        #pragma unroll
        for (int mt = 0; mt < 4; mt++) {
            int r0 = rowBase + warpM + mt * 16 + lr;
            if (r0 < M) {
                float o0 = acc[mt][nt][0] + b0, o1 = acc[mt][nt][1] + b1;
                *(__half2*)(C + (size_t)r0 * 256 + col) = __floats2half2_rn(o0, o1);
                ls[nt * 2]     += o0;  ls2[nt * 2]     = fmaf(o0, o0, ls2[nt * 2]);
                ls[nt * 2 + 1] += o1;  ls2[nt * 2 + 1] = fmaf(o1, o1, ls2[nt * 2 + 1]);
            }
            int r1 = r0 + 8;
            if (r1 < M) {
                float o2 = acc[mt][nt][2] + b0, o3 = acc[mt][nt][3] + b1;
                *(__half2*)(C + (size_t)r1 * 256 + col) = __floats2half2_rn(o2, o3);
                ls[nt * 2]     += o2;  ls2[nt * 2]     = fmaf(o2, o2, ls2[nt * 2]);
                ls[nt * 2 + 1] += o3;  ls2[nt * 2 + 1] = fmaf(o3, o3, ls2[nt * 2 + 1]);
            }
        }
    }
    __syncthreads();
    #pragma unroll
    for (int nt = 0; nt < 4; nt++) {
        int c0 = warpN + nt * 8 + 2 * lc;
        atomicAdd(&s_s[c0],      ls[nt * 2]);
        atomicAdd(&s_s2[c0],     ls2[nt * 2]);
        atomicAdd(&s_s[c0 + 1],  ls[nt * 2 + 1]);
        atomicAdd(&s_s2[c0 + 1], ls2[nt * 2 + 1]);
    }
    __syncthreads();
    if (t < 128) {
        atomicAdd(&g_sumf[colBase + t],  s_s[t]);
        atomicAdd(&g_sum2f[colBase + t], s_s2[t]);
    }
    __threadfence();
    __syncthreads();

    // last block computes BN params (scale/shift), resets stats + counter
    if (t == 0) {
        int total = gridDim.x * gridDim.y;
        int c = atomicAdd(&g_ctr[LAYER - 1], 1);
        isLast = (c == total - 1);
        if (isLast) g_ctr[LAYER - 1] = 0;   // reset for next replay (only last block)
    }
    __syncthreads();
    if (isLast) {
        float s = g_sumf[t], s2 = g_sum2f[t];
        g_sumf[t] = 0.f;
        g_sum2f[t] = 0.f;
        float inv_n = 1.f / (float)M;
        float mean = s * inv_n;
        float var  = fmaf(s2, inv_n, -mean * mean);
        float rs = rsqrtf(var + 1e-5f);
        float sc = rs * bn_g[t];
        g_scale[t] = sc;
        g_shift[t] = bn_be[t] - mean * sc;
    }
}

// ---------------- fp16 TC GEMM40: g_p3h[M,40] = dinv*(f2(g_mh) @ W3) ------------
__global__ __launch_bounds__(256) void k_gemm40_tc(int M) {
    const __half* __restrict__ A = g_mh;
    __shared__ uint32_t Bs2[128][OUTD];   // [k2][n] half2 {W[2k2],W[2k2+1]}
    __shared__ uint32_t As2[16][TPAD];    // [k2 within 32-k step][m]
    __shared__ float ssc[HID], ssh[HID];

    int t = threadIdx.x;
    int warp = t >> 5, lane = t & 31;
    int lr = lane >> 2, lc = lane & 3;
    int rowBase = blockIdx.x * 128;
    int warpM = warp * 16;

    ssc[t] = g_scale[t];
    ssh[t] = g_shift[t];
    for (int s = t; s < 128 * OUTD; s += 256)
        ((uint32_t*)Bs2)[ (s / OUTD) * OUTD + (s % OUTD) ] = g_w3h[s];
    __syncthreads();

    float acc[5][4];
    #pragma unroll
    for (int nt = 0; nt < 5; nt++)
        #pragma unroll
        for (int j = 0; j < 4; j++) acc[nt][j] = 0.f;

    for (int kk = 0; kk < HID; kk += 32) {
        #pragma unroll
        for (int s = t; s < 512; s += 256) {
            int row = s >> 2;
            int k8 = (s & 3) << 3;
            int r = rowBase + row;
            float f[8] = {0.f, 0.f, 0.f, 0.f, 0.f, 0.f, 0.f, 0.f};
            if (r < M) {
                uint4 u = *(const uint4*)(A + (size_t)r * HID + kk + k8);
                h8f(u, f);
            }
            int c = kk + k8;
            #pragma unroll
            for (int j = 0; j < 8; j++)
                f[j] = fmaxf(fmaf(f[j], ssc[c + j], ssh[c + j]), 0.f);
            int k2 = k8 >> 1;
            As2[k2 + 0][row] = pack2h(f[0], f[1]);
            As2[k2 + 1][row] = pack2h(f[2], f[3]);
            As2[k2 + 2][row] = pack2h(f[4], f[5]);
            As2[k2 + 3][row] = pack2h(f[6], f[7]);
        }
        __syncthreads();

        int kk2 = kk >> 1;
        #pragma unroll
        for (int s = 0; s < 2; s++) {
            int kc2 = s * 8;
            uint32_t af[4];
            int m = warpM + lr;
            af[0] = As2[kc2 + lc][m];
            af[1] = As2[kc2 + lc][m + 8];
            af[2] = As2[kc2 + 4 + lc][m];
            af[3] = As2[kc2 + 4 + lc][m + 8];
            #pragma unroll
            for (int nt = 0; nt < 5; nt++) {
                int nc = nt * 8 + lr;
                uint32_t bf[2];
                bf[0] = Bs2[kk2 + kc2 + lc][nc];
                bf[1] = Bs2[kk2 + kc2 + 4 + lc][nc];
                mma_f16(acc[nt], af, bf);
            }
        }
        __syncthreads();
    }

    int r0 = rowBase + warpM + lr;
    int r1 = r0 + 8;
    float d0 = (r0 < M) ? g_dinv[r0] : 0.f;
    float d1 = (r1 < M) ? g_dinv[r1] : 0.f;
    #pragma unroll
    for (int nt = 0; nt < 5; nt++) {
        int col = nt * 8 + 2 * lc;
        if (r0 < M)
            *(uint32_t*)(g_p3h + (size_t)r0 * OUTD + col) =
                pack2h(acc[nt][0] * d0, acc[nt][1] * d0);
        if (r1 < M)
            *(uint32_t*)(g_p3h + (size_t)r1 * OUTD + col) =
                pack2h(acc[nt][2] * d1, acc[nt][3] * d1);
    }
}

// ---------------- fused: gather p3h + b3, then log_softmax(h3 @ Wl + bl) --------
__global__ void k_final40(const float* __restrict__ Wl, const float* __restrict__ bl,
                          const float* __restrict__ b3, float* __restrict__ out, int n) {
    __shared__ float sW[OUTD * OUTD];
    __shared__ float sb[OUTD], sb3[OUTD];
    int tid = threadIdx.x;  // 256
    for (int i = tid; i < OUTD * OUTD; i += 256) sW[i] = Wl[i];
    if (tid < OUTD) { sb[tid] = bl[tid]; sb3[tid] = b3[tid]; }
    __syncthreads();
    int warp = tid >> 5, lane = tid & 31;
    int node = blockIdx.x * 8 + warp;
    if (node >= n) return;

    float a[4] = {0.f, 0.f, 0.f, 0.f};
    if (lane < 10) {
        const uint2* p2 = (const uint2*)g_p3h;   // 10 uint2 per row
        uint2 u = p2[(size_t)node * 10 + lane];
        h4f(u, a);
        int e0 = g_rowptr[node], e1 = g_rowptr[node + 1];
        for (int e = e0; e < e1; e++) {
            float f[4];
            h4f(p2[(size_t)g_col[e] * 10 + lane], f);
            a[0] += f[0]; a[1] += f[1]; a[2] += f[2]; a[3] += f[3];
        }
        float di = g_dinv[node];
        #pragma unroll
        for (int j = 0; j < 4; j++) a[j] = a[j] * di + sb3[lane * 4 + j];
    }

    float z0 = sb[lane];
    float z1 = (lane < 8) ? sb[32 + lane] : -1e30f;
    #pragma unroll
    for (int k = 0; k < OUTD; k++) {
        float hk = __shfl_sync(0xFFFFFFFFu, a[k & 3], k >> 2);
        z0 = fmaf(hk, sW[k * OUTD + lane], z0);
        if (lane < 8) z1 = fmaf(hk, sW[k * OUTD + 32 + lane], z1);
    }
    float mx = fmaxf(z0, z1);
    #pragma unroll
    for (int o = 16; o; o >>= 1) mx = fmaxf(mx, __shfl_xor_sync(0xFFFFFFFFu, mx, o));
    float es = expf(z0 - mx) + ((lane < 8) ? expf(z1 - mx) : 0.f);
    #pragma unroll
    for (int o = 16; o; o >>= 1) es += __shfl_xor_sync(0xFFFFFFFFu, es, o);
    float L = mx + logf(es);
    out[(size_t)node * OUTD + lane] = z0 - L;
    if (lane < 8) out[(size_t)node * OUTD + 32 + lane] = z1 - L;
}

// ---------------- launch (kernel launches ONLY — no CUDA API calls) ------------
extern "C" void kernel_launch(void* const* d_in, const int* in_sizes, int n_in,
                              void* d_out, int out_size) {
    const float* x   = (const float*)d_in[0];
    const int*   ei  = (const int*)d_in[1];      // int32 edge_index (JAX default)
    const float* W1  = (const float*)d_in[2];
    const float* b1  = (const float*)d_in[3];
    const float* g1  = (const float*)d_in[4];
    const float* be1 = (const float*)d_in[5];
    const float* W2  = (const float*)d_in[6];
    const float* b2  = (const float*)d_in[7];
    const float* g2  = (const float*)d_in[8];
    const float* be2 = (const float*)d_in[9];
    const float* W3  = (const float*)d_in[10];
    const float* b3  = (const float*)d_in[11];
    const float* Wl  = (const float*)d_in[12];
    const float* bl  = (const float*)d_in[13];
    float* out = (float*)d_out;

    int n = in_sizes[0] / INF;     // 50000
    int e = in_sizes[1] / 2;       // 800000
    int nb = (n + 1023) / 1024;    // scan blocks (49)
    int total8 = n * INF / 8;      // 800000

    int prepN = (e > total8 ? e : total8);
    k_prep<<<(prepN + 255) / 256, 256>>>(ei, x, W1, W2, W3, e, n, total8);
    k_scan1<<<nb, 1024>>>(n);
    k_scan23<<<nb, 1024>>>(n, nb);
    k_scatter<<<(e + 255) / 256, 256>>>(ei, e, n);

    // layer 1: aggregate-first (width 128 fp16), then fp16 TC GEMM (BN fused)
    k_aggX<<<(n + 7) / 8, 256>>>(n);
    dim3 gg((n + 127) / 128, 2);
    k_gemm256_tc<1><<<gg, 256>>>(b1, g1, be1, n);

    // layer 2: aggregate f1(m1) (width 256 fp16, half2 BN), then GEMM (BN fused)
    k_agg256<<<(n + 7) / 8, 256>>>(n);
    k_gemm256_tc<2><<<gg, 256>>>(b2, g2, be2, n);

    // layer 3: fp16 TC GEMM (f2 fused into A-fill, dinv in epilogue)
    k_gemm40_tc<<<(n + 127) / 128, 256>>>(n);

    // fused width-40 aggregation + final linear + log_softmax
    k_final40<<<(n + 7) / 8, 256>>>(Wl, bl, b3, out, n);
}

// round 17
// speedup vs baseline: 1.0026x; 1.0026x over previous
#include <cuda_runtime.h>
#include <cuda_fp16.h>
#include <math.h>
#include <stdint.h>

#define NN 50000
#define EE 800000
#define INF 128
#define HID 256
#define OUTD 40

// ---------------- scratch (static device globals; no allocation) -------------
__device__ int    g_deg[NN];        // indeg (self-loop added analytically)
__device__ float  g_dinv[NN];
__device__ int    g_rowptr[NN + 1];
__device__ int    g_cursor[NN];
__device__ int    g_col[EE];
__device__ int    g_bsum[64];
__device__ int    g_ctr[2];         // scan spin counters (loader zero-init, self-reset)
__device__ __align__(16) __half g_xh[(size_t)NN * INF];    // x in fp16
__device__ __align__(16) __half g_aggxh[(size_t)NN * INF]; // Â x (fp16)
__device__ __align__(16) __half g_mh[(size_t)NN * HID];    // conv outputs m1/m2 (fp16)
__device__ __align__(16) __half g_aggh[(size_t)NN * HID];  // Â f1(m1) (fp16)
__device__ __align__(16) __half g_p3h[(size_t)NN * OUTD];  // dinv*(f2(m2)@W3) fp16
__device__ __align__(16) uint32_t g_w1h[64 * 256];         // W1 k-pair fp16
__device__ __align__(16) uint32_t g_w2h[128 * 256];        // W2 k-pair fp16
__device__ __align__(16) uint32_t g_w3h[128 * OUTD];       // W3 k-pair fp16
__device__ float  g_sumf[HID];     // fused BN stats (fp32, atomic)
__device__ float  g_sum2f[HID];
__device__ float  g_scale[HID];
__device__ float  g_shift[HID];

// ---------------- half pack/unpack helpers -------------------------------------
__device__ __forceinline__ void h4f(uint2 u, float f[4]) {
    float2 p0 = __half22float2(*(__half2*)&u.x);
    float2 p1 = __half22float2(*(__half2*)&u.y);
    f[0] = p0.x; f[1] = p0.y; f[2] = p1.x; f[3] = p1.y;
}
__device__ __forceinline__ uint2 f4h(const float f[4]) {
    __half2 h0 = __floats2half2_rn(f[0], f[1]);
    __half2 h1 = __floats2half2_rn(f[2], f[3]);
    uint2 u;
    u.x = *(uint32_t*)&h0;
    u.y = *(uint32_t*)&h1;
    return u;
}
__device__ __forceinline__ void h8f(uint4 u, float f[8]) {
    h4f(make_uint2(u.x, u.y), f);
    h4f(make_uint2(u.z, u.w), f + 4);
}
__device__ __forceinline__ uint4 f8h(const float f[8]) {
    uint2 a = f4h(f), b = f4h(f + 4);
    return make_uint4(a.x, a.y, b.x, b.y);
}
__device__ __forceinline__ uint32_t pack2h(float a, float b) {
    __half2 h = __floats2half2_rn(a, b);
    return *(uint32_t*)&h;
}
__device__ __forceinline__ void cp16(void* smem, const void* g) {
    uint32_t sa = (uint32_t)__cvta_generic_to_shared(smem);
    asm volatile("cp.async.cg.shared.global [%0], [%1], 16;" :: "r"(sa), "l"(g));
}

// ---------------- merged preprocessing: wconv + xtoh + deg ----------------------
__global__ void k_prep(const int* __restrict__ ei,
                       const float* __restrict__ x,
                       const float* __restrict__ W1,
                       const float* __restrict__ W2,
                       const float* __restrict__ W3,
                       int e, int n, int total8) {
    int i = blockIdx.x * blockDim.x + threadIdx.x;
    if (i < total8) {
        float4 a = ((const float4*)x)[i * 2];
        float4 b = ((const float4*)x)[i * 2 + 1];
        float f[8] = {a.x, a.y, a.z, a.w, b.x, b.y, b.z, b.w};
        ((uint4*)g_xh)[i] = f8h(f);
    }
    if (i < e) {
        int d = ei[e + i];
        if ((unsigned)d < (unsigned)n) atomicAdd(&g_deg[d], 1);
    }
    if (i < 64 * 256) {
        int k2 = i >> 8, nc = i & 255;
        g_w1h[i] = pack2h(W1[(size_t)(2 * k2) * 256 + nc], W1[(size_t)(2 * k2 + 1) * 256 + nc]);
    }
    if (i < 128 * 256) {
        int k2 = i >> 8, nc = i & 255;
        g_w2h[i] = pack2h(W2[(size_t)(2 * k2) * 256 + nc], W2[(size_t)(2 * k2 + 1) * 256 + nc]);
    }
    if (i < 128 * OUTD) {
        int k2 = i / OUTD, nc = i % OUTD;
        g_w3h[i] = pack2h(W3[(size_t)(2 * k2) * OUTD + nc], W3[(size_t)(2 * k2 + 1) * OUTD + nc]);
    }
}

// ---------------- merged CSR scan (phases 1+2+3 in one kernel) -------------------
// nb <= 64 blocks, all co-resident on 148 SMs -> grid spin is deadlock-free.
__global__ __launch_bounds__(1024) void k_scan(int n, int nb) {
    __shared__ int warpsums[32];
    __shared__ int w0s;
    __shared__ int s_off;
    int b = blockIdx.x, tid = threadIdx.x;
    int i = b * 1024 + tid;

    // phase A: per-block inclusive scan of indeg
    int v = 0;
    if (i < n) {
        int d = g_deg[i];
        v = d;
        g_dinv[i] = rsqrtf((float)(d + 1));
    }
    int x = v;
    #pragma unroll
    for (int o = 1; o < 32; o <<= 1) {
        int y = __shfl_up_sync(0xFFFFFFFFu, x, o);
        if ((tid & 31) >= o) x += y;
    }
    if ((tid & 31) == 31) warpsums[tid >> 5] = x;
    __syncthreads();
    if (tid < 32) {
        int w = warpsums[tid];
        #pragma unroll
        for (int o = 1; o < 32; o <<= 1) {
            int y = __shfl_up_sync(0xFFFFFFFFu, w, o);
            if (tid >= o) w += y;
        }
        warpsums[tid] = w;
    }
    __syncthreads();
    int incl = x + ((tid >= 32) ? warpsums[(tid >> 5) - 1] : 0);
    if (i < n) g_rowptr[i + 1] = incl;
    if (tid == 1023) {
        g_bsum[b] = incl;
        __threadfence();
    }
    __syncthreads();

    // publish + spin until all blocks published their totals
    if (tid == 0) {
        atomicAdd(&g_ctr[0], 1);
        while (atomicAdd(&g_ctr[0], 0) < nb) {}
    }
    __syncthreads();

    // phase B: scan block totals, pick this block's exclusive offset
    int v2 = 0, x2 = 0;
    if (tid < 64) {
        v2 = (tid < nb) ? g_bsum[tid] : 0;
        x2 = v2;
        #pragma unroll
        for (int o = 1; o < 32; o <<= 1) {
            int y = __shfl_up_sync(0xFFFFFFFFu, x2, o);
            if ((tid & 31) >= o) x2 += y;
        }
        if (tid == 31) w0s = x2;
    }
    __syncthreads();
    if (tid < 64) {
        int incl2 = x2 + ((tid >= 32) ? w0s : 0);
        if (tid == b) s_off = incl2 - v2;
    }
    __syncthreads();

    // phase C: finalize rowptr + cursor, reset deg
    if (i < n) {
        int indeg = g_deg[i];
        int val = g_rowptr[i + 1] + s_off;
        g_rowptr[i + 1] = val;
        g_cursor[i] = val - indeg;
        g_deg[i] = 0;                               // reset for next replay
    }
    if (i == 0) g_rowptr[0] = 0;

    // counter reset: last block through phase C resets both (all blocks have
    // already exited the spin by the time ctr[1] reaches nb)
    __syncthreads();
    if (tid == 0) {
        int c = atomicAdd(&g_ctr[1], 1);
        if (c == nb - 1) { g_ctr[0] = 0; g_ctr[1] = 0; }
    }
}

__global__ void k_scatter(const int* __restrict__ ei, int e, int n) {
    int i = blockIdx.x * blockDim.x + threadIdx.x;
    if (i < e) {
        int s = ei[i], d = ei[e + i];
        if ((unsigned)d < (unsigned)n) {
            s = min(max(s, 0), n - 1);
            int pos = atomicAdd(&g_cursor[d], 1);
            g_col[pos] = s;
        }
    }
}

// ---------------- aggregation kernels (warp-per-node, 4-wide unroll) -------------
__global__ __launch_bounds__(256) void k_aggX(int n) {
    int node = blockIdx.x * 8 + (threadIdx.x >> 5);
    int lane = threadIdx.x & 31;
    if (node >= n) return;
    const uint2* __restrict__ x2 = (const uint2*)g_xh;   // 32 uint2 per row
    float di = g_dinv[node];
    float acc[4], f[4];
    h4f(x2[(size_t)node * 32 + lane], f);
    #pragma unroll
    for (int j = 0; j < 4; j++) acc[j] = di * f[j];
    int e0 = g_rowptr[node], e1 = g_rowptr[node + 1];
    int e = e0;
    for (; e + 3 < e1; e += 4) {
        int s0 = g_col[e], s1 = g_col[e + 1], s2 = g_col[e + 2], s3 = g_col[e + 3];
        float d0 = g_dinv[s0], d1 = g_dinv[s1], d2 = g_dinv[s2], d3 = g_dinv[s3];
        float f0[4], f1[4], f2[4], f3[4];
        h4f(x2[(size_t)s0 * 32 + lane], f0);
        h4f(x2[(size_t)s1 * 32 + lane], f1);
        h4f(x2[(size_t)s2 * 32 + lane], f2);
        h4f(x2[(size_t)s3 * 32 + lane], f3);
        #pragma unroll
        for (int j = 0; j < 4; j++)
            acc[j] += (d0 * f0[j] + d1 * f1[j]) + (d2 * f2[j] + d3 * f3[j]);
    }
    for (; e < e1; e++) {
        int s = g_col[e];
        float d = g_dinv[s];
        h4f(x2[(size_t)s * 32 + lane], f);
        #pragma unroll
        for (int j = 0; j < 4; j++) acc[j] += d * f[j];
    }
    #pragma unroll
    for (int j = 0; j < 4; j++) acc[j] *= di;
    ((uint2*)g_aggxh)[(size_t)node * 32 + lane] = f4h(acc);
}

// agg with BN+ReLU applied in packed fp16 (half2), fp32 accumulation
__global__ __launch_bounds__(256) void k_agg256(int n) {
    int node = blockIdx.x * 8 + (threadIdx.x >> 5);
    int lane = threadIdx.x & 31;
    if (node >= n) return;
    const uint4* __restrict__ m4 = (const uint4*)g_mh;   // 32 uint4 per row
    __half2 sc2[4], sh2[4];
    {
        float4 s0 = ((const float4*)g_scale)[2 * lane];
        float4 s1 = ((const float4*)g_scale)[2 * lane + 1];
        float4 h0 = ((const float4*)g_shift)[2 * lane];
        float4 h1 = ((const float4*)g_shift)[2 * lane + 1];
        sc2[0] = __floats2half2_rn(s0.x, s0.y); sc2[1] = __floats2half2_rn(s0.z, s0.w);
        sc2[2] = __floats2half2_rn(s1.x, s1.y); sc2[3] = __floats2half2_rn(s1.z, s1.w);
        sh2[0] = __floats2half2_rn(h0.x, h0.y); sh2[1] = __floats2half2_rn(h0.z, h0.w);
        sh2[2] = __floats2half2_rn(h1.x, h1.y); sh2[3] = __floats2half2_rn(h1.z, h1.w);
    }
    const __half2 zero2 = __floats2half2_rn(0.f, 0.f);
    float di = g_dinv[node];
    float acc[8];
    #pragma unroll
    for (int j = 0; j < 8; j++) acc[j] = 0.f;

    auto accum = [&](uint4 u, float d) {
        uint32_t w[4] = {u.x, u.y, u.z, u.w};
        #pragma unroll
        for (int j = 0; j < 4; j++) {
            __half2 v = *(__half2*)&w[j];
            v = __hmax2(__hfma2(v, sc2[j], sh2[j]), zero2);
            float2 p = __half22float2(v);
            acc[2 * j]     = fmaf(d, p.x, acc[2 * j]);
            acc[2 * j + 1] = fmaf(d, p.y, acc[2 * j + 1]);
        }
    };

    accum(m4[(size_t)node * 32 + lane], di);   // self loop
    int e0 = g_rowptr[node], e1 = g_rowptr[node + 1];
    int e = e0;
    for (; e + 3 < e1; e += 4) {
        int s0 = g_col[e], s1 = g_col[e + 1], s2 = g_col[e + 2], s3 = g_col[e + 3];
        float d0 = g_dinv[s0], d1 = g_dinv[s1], d2 = g_dinv[s2], d3 = g_dinv[s3];
        uint4 u0 = m4[(size_t)s0 * 32 + lane];
        uint4 u1 = m4[(size_t)s1 * 32 + lane];
        uint4 u2 = m4[(size_t)s2 * 32 + lane];
        uint4 u3 = m4[(size_t)s3 * 32 + lane];
        accum(u0, d0);
        accum(u1, d1);
        accum(u2, d2);
        accum(u3, d3);
    }
    for (; e < e1; e++) {
        int s = g_col[e];
        accum(m4[(size_t)s * 32 + lane], g_dinv[s]);
    }
    #pragma unroll
    for (int j = 0; j < 8; j++) acc[j] *= di;
    ((uint4*)g_aggh)[(size_t)node * 32 + lane] = f8h(acc);
}

// ---------------- fp16 m16n8k16 MMA helper --------------------------------------
__device__ __forceinline__ void mma_f16(float c[4], const uint32_t a[4], const uint32_t b[2]) {
    asm volatile(
        "mma.sync.aligned.m16n8k16.row.col.f32.f16.f16.f32 "
        "{%0,%1,%2,%3}, {%4,%5,%6,%7}, {%8,%9}, {%0,%1,%2,%3};"
        : "+f"(c[0]), "+f"(c[1]), "+f"(c[2]), "+f"(c[3])
        : "r"(a[0]), "r"(a[1]), "r"(a[2]), "r"(a[3]), "r"(b[0]), "r"(b[1]));
}

#define TPAD 136    // B word stride: 136 % 32 == 8 -> conflict-free
#define ASTRIDE 20  // A word stride: {k*20 mod 32} covers all banks

// ---------------- fp16 TC GEMM (cp.async double-buffered) -----------------------
// C_h[M,256] = A_h[M,K] @ Wh[K,256] + bias ; BN stats fused (params separate).
template <int LAYER>
__global__ __launch_bounds__(256) void k_gemm256_tc(
    const float* __restrict__ bias, int M) {
    constexpr int K = (LAYER == 1) ? INF : HID;
    constexpr int NSTEP = K / 32;
    const __half* __restrict__ A = (LAYER == 1) ? g_aggxh : g_aggh;
    const uint32_t* __restrict__ Bw = (LAYER == 1) ? g_w1h : g_w2h;  // [K/2][256]
    __half* __restrict__ C = g_mh;

    __shared__ uint32_t As[2][128][ASTRIDE];  // [stage][m][k2] (16 of 20 used)
    __shared__ uint32_t Bs[2][16][TPAD];      // [stage][k2][n]
    __shared__ float s_s[128], s_s2[128];

    int t = threadIdx.x;
    int warp = t >> 5, lane = t & 31;
    int lr = lane >> 2, lc = lane & 3;
    int warpM = (warp >> 2) * 64;
    int warpN = (warp & 3) * 32;
    int rowBase = blockIdx.x * 128;
    int colBase = blockIdx.y * 128;

    if (t < 128) { s_s[t] = 0.f; s_s2[t] = 0.f; }

    float acc[4][4][4];
    #pragma unroll
    for (int mt = 0; mt < 4; mt++)
        #pragma unroll
        for (int nt = 0; nt < 4; nt++)
            #pragma unroll
            for (int j = 0; j < 4; j++) acc[mt][nt][j] = 0.f;

    auto load_stage = [&](int st, int kk) {
        #pragma unroll
        for (int h = 0; h < 2; h++) {
            int s = t + h * 256;
            int row = s >> 2;
            int c4 = (s & 3) << 2;                 // uint32 offset in row
            int r = min(rowBase + row, M - 1);     // clamp: dup rows, results unused
            cp16(&As[st][row][c4], A + (size_t)r * K + kk + (c4 << 1));
        }
        int kk2 = kk >> 1;
        #pragma unroll
        for (int h = 0; h < 2; h++) {
            int s = t + h * 256;
            int k2 = s >> 5;
            int n4 = (s & 31) << 2;
            cp16(&Bs[st][k2][n4], Bw + (size_t)(kk2 + k2) * 256 + colBase + n4);
        }
        asm volatile("cp.async.commit_group;");
    };

    load_stage(0, 0);
    #pragma unroll
    for (int i = 0; i < NSTEP; i++) {
        if (i + 1 < NSTEP) {
            load_stage((i + 1) & 1, (i + 1) * 32);
            asm volatile("cp.async.wait_group 1;");
        } else {
            asm volatile("cp.async.wait_group 0;");
        }
        __syncthreads();
        int st = i & 1;
        #pragma unroll
        for (int s = 0; s < 2; s++) {
            int kc2 = s * 8;
            uint32_t af[4][4], bf[4][2];
            #pragma unroll
            for (int nt = 0; nt < 4; nt++) {
                int nc = warpN + nt * 8 + lr;
                bf[nt][0] = Bs[st][kc2 + lc][nc];
                bf[nt][1] = Bs[st][kc2 + 4 + lc][nc];
            }
            #pragma unroll
            for (int mt = 0; mt < 4; mt++) {
                int m = warpM + mt * 16 + lr;
                af[mt][0] = As[st][m][kc2 + lc];
                af[mt][1] = As[st][m + 8][kc2 + lc];
                af[mt][2] = As[st][m][kc2 + 4 + lc];
                af[mt][3] = As[st][m + 8][kc2 + 4 + lc];
            }
            #pragma unroll
            for (int mt = 0; mt < 4; mt++)
                #pragma unroll
                for (int nt = 0; nt < 4; nt++)
                    mma_f16(acc[mt][nt], af[mt], bf[nt]);
        }
        __syncthreads();
    }

    // epilogue: bias add + half store + fused BN-stat accumulation (fp32)
    float ls[8], ls2[8];
    #pragma unroll
    for (int j = 0; j < 8; j++) { ls[j] = 0.f; ls2[j] = 0.f; }

    #pragma unroll
    for (int nt = 0; nt < 4; nt++) {
        int col = colBase + warpN + nt * 8 + 2 * lc;
        float b0 = bias[col], b1 = bias[col + 1];
        #pragma unroll
        for (int mt = 0; mt < 4; mt++) {
            int r0 = rowBase + warpM + mt * 16 + lr;
            if (r0 < M) {
                float o0 = acc[mt][nt][0] + b0, o1 = acc[mt][nt][1] + b1;
                *(__half2*)(C + (size_t)r0 * 256 + col) = __floats2half2_rn(o0, o1);
                ls[nt * 2]     += o0;  ls2[nt * 2]     = fmaf(o0, o0, ls2[nt * 2]);
                ls[nt * 2 + 1] += o1;  ls2[nt * 2 + 1] = fmaf(o1, o1, ls2[nt * 2 + 1]);
            }
            int r1 = r0 + 8;
            if (r1 < M) {
                float o2 = acc[mt][nt][2] + b0, o3 = acc[mt][nt][3] + b1;
                *(__half2*)(C + (size_t)r1 * 256 + col) = __floats2half2_rn(o2, o3);
                ls[nt * 2]     += o2;  ls2[nt * 2]     = fmaf(o2, o2, ls2[nt * 2]);
                ls[nt * 2 + 1] += o3;  ls2[nt * 2 + 1] = fmaf(o3, o3, ls2[nt * 2 + 1]);
            }
        }
    }
    __syncthreads();
    #pragma unroll
    for (int nt = 0; nt < 4; nt++) {
        int c0 = warpN + nt * 8 + 2 * lc;
        atomicAdd(&s_s[c0],      ls[nt * 2]);
        atomicAdd(&s_s2[c0],     ls2[nt * 2]);
        atomicAdd(&s_s[c0 + 1],  ls[nt * 2 + 1]);
        atomicAdd(&s_s2[c0 + 1], ls2[nt * 2 + 1]);
    }
    __syncthreads();
    if (t < 128) {
        atomicAdd(&g_sumf[colBase + t],  s_s[t]);
        atomicAdd(&g_sum2f[colBase + t], s_s2[t]);
    }
}

// ---------------- BN params from fused stats -----------------------------------
__global__ void k_bnparams(const float* __restrict__ g, const float* __restrict__ be, int n) {
    int t = threadIdx.x;  // 256
    float s = g_sumf[t], s2 = g_sum2f[t];
    g_sumf[t] = 0.f;
    g_sum2f[t] = 0.f;
    float inv_n = 1.f / (float)n;
    float mean = s * inv_n;
    float var  = fmaf(s2, inv_n, -mean * mean);
    float rs = rsqrtf(var + 1e-5f);
    float sc = rs * g[t];
    g_scale[t] = sc;
    g_shift[t] = be[t] - mean * sc;
}

// ---------------- fp16 TC GEMM40: g_p3h[M,40] = dinv*(f2(g_mh) @ W3) ------------
__global__ __launch_bounds__(256) void k_gemm40_tc(int M) {
    const __half* __restrict__ A = g_mh;
    __shared__ uint32_t Bs2[128][OUTD];   // [k2][n] half2 {W[2k2],W[2k2+1]}
    __shared__ uint32_t As2[16][TPAD];    // [k2 within 32-k step][m]
    __shared__ float ssc[HID], ssh[HID];

    int t = threadIdx.x;
    int warp = t >> 5, lane = t & 31;
    int lr = lane >> 2, lc = lane & 3;
    int rowBase = blockIdx.x * 128;
    int warpM = warp * 16;

    ssc[t] = g_scale[t];
    ssh[t] = g_shift[t];
    for (int s = t; s < 128 * OUTD; s += 256)
        ((uint32_t*)Bs2)[ (s / OUTD) * OUTD + (s % OUTD) ] = g_w3h[s];
    __syncthreads();

    float acc[5][4];
    #pragma unroll
    for (int nt = 0; nt < 5; nt++)
        #pragma unroll
        for (int j = 0; j < 4; j++) acc[nt][j] = 0.f;

    for (int kk = 0; kk < HID; kk += 32) {
        #pragma unroll
        for (int s = t; s < 512; s += 256) {
            int row = s >> 2;
            int k8 = (s & 3) << 3;
            int r = rowBase + row;
            float f[8] = {0.f, 0.f, 0.f, 0.f, 0.f, 0.f, 0.f, 0.f};
            if (r < M) {
                uint4 u = *(const uint4*)(A + (size_t)r * HID + kk + k8);
                h8f(u, f);
            }
            int c = kk + k8;
            #pragma unroll
            for (int j = 0; j < 8; j++)
                f[j] = fmaxf(fmaf(f[j], ssc[c + j], ssh[c + j]), 0.f);
            int k2 = k8 >> 1;
            As2[k2 + 0][row] = pack2h(f[0], f[1]);
            As2[k2 + 1][row] = pack2h(f[2], f[3]);
            As2[k2 + 2][row] = pack2h(f[4], f[5]);
            As2[k2 + 3][row] = pack2h(f[6], f[7]);
        }
        __syncthreads();

        int kk2 = kk >> 1;
        #pragma unroll
        for (int s = 0; s < 2; s++) {
            int kc2 = s * 8;
            uint32_t af[4];
            int m = warpM + lr;
            af[0] = As2[kc2 + lc][m];
            af[1] = As2[kc2 + lc][m + 8];
            af[2] = As2[kc2 + 4 + lc][m];
            af[3] = As2[kc2 + 4 + lc][m + 8];
            #pragma unroll
            for (int nt = 0; nt < 5; nt++) {
                int nc = nt * 8 + lr;
                uint32_t bf[2];
                bf[0] = Bs2[kk2 + kc2 + lc][nc];
                bf[1] = Bs2[kk2 + kc2 + 4 + lc][nc];
                mma_f16(acc[nt], af, bf);
            }
        }
        __syncthreads();
    }

    int r0 = rowBase + warpM + lr;
    int r1 = r0 + 8;
    float d0 = (r0 < M) ? g_dinv[r0] : 0.f;
    float d1 = (r1 < M) ? g_dinv[r1] : 0.f;
    #pragma unroll
    for (int nt = 0; nt < 5; nt++) {
        int col = nt * 8 + 2 * lc;
        if (r0 < M)
            *(uint32_t*)(g_p3h + (size_t)r0 * OUTD + col) =
                pack2h(acc[nt][0] * d0, acc[nt][1] * d0);
        if (r1 < M)
            *(uint32_t*)(g_p3h + (size_t)r1 * OUTD + col) =
                pack2h(acc[nt][2] * d1, acc[nt][3] * d1);
    }
}

// ---------------- fused: gather p3h + b3, then log_softmax(h3 @ Wl + bl) --------
// Dual-edge gather: lanes 0-9 take even edges, lanes 16-25 take odd edges.
__global__ void k_final40(const float* __restrict__ Wl, const float* __restrict__ bl,
                          const float* __restrict__ b3, float* __restrict__ out, int n) {
    __shared__ float sW[OUTD * OUTD];
    __shared__ float sb[OUTD], sb3[OUTD];
    int tid = threadIdx.x;  // 256
    for (int i = tid; i < OUTD * OUTD; i += 256) sW[i] = Wl[i];
    if (tid < OUTD) { sb[tid] = bl[tid]; sb3[tid] = b3[tid]; }
    __syncthreads();
    int warp = tid >> 5, lane = tid & 31;
    int node = blockIdx.x * 8 + warp;
    if (node >= n) return;

    const uint2* __restrict__ p2 = (const uint2*)g_p3h;   // 10 uint2 per row
    bool low  = lane < 10;
    bool high = (lane >= 16) && (lane < 26);
    int li = low ? lane : (high ? lane - 16 : 0);

    float a[4] = {0.f, 0.f, 0.f, 0.f};
    if (low) {
        float f[4];
        h4f(p2[(size_t)node * 10 + lane], f);
        a[0] = f[0]; a[1] = f[1]; a[2] = f[2]; a[3] = f[3];
    }
    int e0 = g_rowptr[node], e1 = g_rowptr[node + 1];
    for (int e = e0; e < e1; e += 2) {
        int idx = low ? e : ((high && (e + 1 < e1)) ? e + 1 : -1);
        if (idx >= 0) {
            float f[4];
            h4f(p2[(size_t)g_col[idx] * 10 + li], f);
            a[0] += f[0]; a[1] += f[1]; a[2] += f[2]; a[3] += f[3];
        }
    }
    // combine odd-edge partials (lanes 16-25) into lanes 0-9
    #pragma unroll
    for (int j = 0; j < 4; j++)
        a[j] += __shfl_down_sync(0xFFFFFFFFu, a[j], 16);
    if (low) {
        float di = g_dinv[node];
        #pragma unroll
        for (int j = 0; j < 4; j++) a[j] = a[j] * di + sb3[lane * 4 + j];
    }

    float z0 = sb[lane];
    float z1 = (lane < 8) ? sb[32 + lane] : -1e30f;
    #pragma unroll
    for (int k = 0; k < OUTD; k++) {
        float hk = __shfl_sync(0xFFFFFFFFu, a[k & 3], k >> 2);
        z0 = fmaf(hk, sW[k * OUTD + lane], z0);
        if (lane < 8) z1 = fmaf(hk, sW[k * OUTD + 32 + lane], z1);
    }
    float mx = fmaxf(z0, z1);
    #pragma unroll
    for (int o = 16; o; o >>= 1) mx = fmaxf(mx, __shfl_xor_sync(0xFFFFFFFFu, mx, o));
    float es = expf(z0 - mx) + ((lane < 8) ? expf(z1 - mx) : 0.f);
    #pragma unroll
    for (int o = 16; o; o >>= 1) es += __shfl_xor_sync(0xFFFFFFFFu, es, o);
    float L = mx + logf(es);
    out[(size_t)node * OUTD + lane] = z0 - L;
    if (lane < 8) out[(size_t)node * OUTD + 32 + lane] = z1 - L;
}

// ---------------- launch (kernel launches ONLY — no CUDA API calls) ------------
extern "C" void kernel_launch(void* const* d_in, const int* in_sizes, int n_in,
                              void* d_out, int out_size) {
    const float* x   = (const float*)d_in[0];
    const int*   ei  = (const int*)d_in[1];      // int32 edge_index (JAX default)
    const float* W1  = (const float*)d_in[2];
    const float* b1  = (const float*)d_in[3];
    const float* g1  = (const float*)d_in[4];
    const float* be1 = (const float*)d_in[5];
    const float* W2  = (const float*)d_in[6];
    const float* b2  = (const float*)d_in[7];
    const float* g2  = (const float*)d_in[8];
    const float* be2 = (const float*)d_in[9];
    const float* W3  = (const float*)d_in[10];
    const float* b3  = (const float*)d_in[11];
    const float* Wl  = (const float*)d_in[12];
    const float* bl  = (const float*)d_in[13];
    float* out = (float*)d_out;

    int n = in_sizes[0] / INF;     // 50000
    int e = in_sizes[1] / 2;       // 800000
    int nb = (n + 1023) / 1024;    // scan blocks (49)
    int total8 = n * INF / 8;      // 800000

    int prepN = (e > total8 ? e : total8);
    k_prep<<<(prepN + 255) / 256, 256>>>(ei, x, W1, W2, W3, e, n, total8);
    k_scan<<<nb, 1024>>>(n, nb);
    k_scatter<<<(e + 255) / 256, 256>>>(ei, e, n);

    // layer 1: aggregate-first (width 128 fp16), then fp16 TC GEMM (stats fused)
    k_aggX<<<(n + 7) / 8, 256>>>(n);
    dim3 gg((n + 127) / 128, 2);
    k_gemm256_tc<1><<<gg, 256>>>(b1, n);
    k_bnparams<<<1, 256>>>(g1, be1, n);

    // layer 2: aggregate f1(m1) (width 256 fp16, half2 BN), then fp16 TC GEMM
    k_agg256<<<(n + 7) / 8, 256>>>(n);
    k_gemm256_tc<2><<<gg, 256>>>(b2, n);
    k_bnparams<<<1, 256>>>(g2, be2, n);

    // layer 3: fp16 TC GEMM (f2 fused into A-fill, dinv in epilogue)
    k_gemm40_tc<<<(n + 127) / 128, 256>>>(n);

    // fused width-40 aggregation + final linear + log_softmax (dual-edge gather)
    k_final40<<<(n + 7) / 8, 256>>>(Wl, bl, b3, out, n);
}